// round 1
// baseline (speedup 1.0000x reference)
#include <cuda_runtime.h>
#include <math.h>

#define E_TOT   131072
#define NEMB    128
#define DIN     384
#define HD1     512
#define HD2     64
#define TILE_E  64
#define NBLK    (E_TOT / TILE_E)   // 2048
#define XSTR    68
#define HSTR    68

// smem layout (floats)
#define OFF_XST   0
#define SZ_XST    (DIN * XSTR)              // 26112
#define OFF_W1S   (OFF_XST + SZ_XST)
#define SZ_W1S    (32 * 64)                 // 2048
#define OFF_H1T   (OFF_W1S + SZ_W1S)
#define SZ_H1T    (64 * HSTR)               // 4352
#define OFF_W2S   (OFF_H1T + SZ_H1T)
#define SZ_W2S    (64 * 64)                 // 4096
#define OFF_H2T   (OFF_W2S + SZ_W2S)
#define SZ_H2T    (64 * HSTR)               // 4352
#define OFF_W3S   (OFF_H2T + SZ_H2T)
#define SZ_W3S    (64 * 128)                // 8192
#define OFF_RED   (OFF_W3S + SZ_W3S)
#define SZ_RED    512
#define SMEM_FLOATS (OFF_RED + SZ_RED)
#define SMEM_BYTES  (SMEM_FLOATS * 4)       // 198656 B

// scratch (static device globals: allocation-free)
__device__ float g_h[(size_t)E_TOT * NEMB];   // 64 MB MLP output
__device__ float g_part[NBLK * 2];            // per-block sum / sumsq
__device__ float g_stats[2];                  // mean, rstd

__device__ __forceinline__ float silu_f(float v) {
    return v / (1.0f + expf(-v));
}

__global__ void __launch_bounds__(256, 1)
pass1_kernel(const float* __restrict__ gx, const float* __restrict__ mx,
             const int* __restrict__ g2me_i, const float* __restrict__ g2me_x,
             const float* __restrict__ W1, const float* __restrict__ b1,
             const float* __restrict__ W2, const float* __restrict__ b2,
             const float* __restrict__ W3, const float* __restrict__ b3)
{
    extern __shared__ float sm[];
    float* xsT = sm + OFF_XST;   // [384][XSTR] : x transposed, xsT[k][e]
    float* W1s = sm + OFF_W1S;   // [32][64]
    float* h1T = sm + OFF_H1T;   // [64][HSTR] : h1 chunk transposed
    float* W2s = sm + OFF_W2S;   // [64][64]
    float* h2T = sm + OFF_H2T;   // [64][HSTR]
    float* W3s = sm + OFF_W3S;   // [64][128]
    float* red = sm + OFF_RED;   // [512]

    const int t  = threadIdx.x;
    const int tx = t & 15;       // edge-group index (e0 = tx*4)
    const int ty = t >> 4;       // output-group index
    const int eb = blockIdx.x * TILE_E;
    const int* __restrict__ rowi = g2me_i;
    const int* __restrict__ coli = g2me_i + E_TOT;

    // ---- gather x^T into smem: [gx[row] | mx[col] | g2me_x] ----
    for (int idx = t; idx < TILE_E * 128; idx += 256) {
        const int e = idx >> 7;
        const int j = idx & 127;
        const int r = rowi[eb + e];
        const int c = coli[eb + e];
        xsT[(j)       * XSTR + e] = gx[(size_t)r * 128 + j];
        xsT[(128 + j) * XSTR + e] = mx[(size_t)c * 128 + j];
        xsT[(256 + j) * XSTR + e] = g2me_x[(size_t)(eb + e) * 128 + j];
    }
    __syncthreads();

    float acc2[16];
#pragma unroll
    for (int i = 0; i < 16; i++) acc2[i] = 0.f;

    // ---- GEMM1 (384->512) in 8 n-chunks of 64, each fused into GEMM2 (512->64) ----
    for (int chunk = 0; chunk < 8; chunk++) {
        const int n0 = chunk * 64;
        float acc1[16];
#pragma unroll
        for (int i = 0; i < 16; i++) acc1[i] = 0.f;

        for (int k0 = 0; k0 < DIN; k0 += 32) {
            // stage W1[k0:k0+32, n0:n0+64]
#pragma unroll
            for (int i = t; i < 512; i += 256) {
                const int kk = i >> 4;
                const int c4 = i & 15;
                ((float4*)W1s)[kk * 16 + c4] =
                    *(const float4*)&W1[(size_t)(k0 + kk) * HD1 + n0 + c4 * 4];
            }
            __syncthreads();
#pragma unroll
            for (int kk = 0; kk < 32; kk++) {
                const float4 xv = *(const float4*)&xsT[(k0 + kk) * XSTR + tx * 4];
                const float4 wv = *(const float4*)&W1s[kk * 64 + ty * 4];
                const float xa[4] = {xv.x, xv.y, xv.z, xv.w};
                const float wa[4] = {wv.x, wv.y, wv.z, wv.w};
#pragma unroll
                for (int i = 0; i < 4; i++)
#pragma unroll
                    for (int j = 0; j < 4; j++)
                        acc1[i * 4 + j] = fmaf(xa[i], wa[j], acc1[i * 4 + j]);
            }
            __syncthreads();
        }

        // bias + SiLU -> h1T[n_local][e]
#pragma unroll
        for (int j = 0; j < 4; j++) {
            const float bj = b1[n0 + ty * 4 + j];
#pragma unroll
            for (int i = 0; i < 4; i++)
                h1T[(ty * 4 + j) * HSTR + tx * 4 + i] = silu_f(acc1[i * 4 + j] + bj);
        }
        // stage W2[n0:n0+64, :]  (contiguous 4096 floats)
#pragma unroll
        for (int i = t; i < 1024; i += 256)
            ((float4*)W2s)[i] = ((const float4*)W2)[(size_t)n0 * 16 + i];
        __syncthreads();

        // GEMM2 partial accumulate: h2[e][j] += h1chunk[e][:] @ W2chunk
#pragma unroll 16
        for (int n = 0; n < 64; n++) {
            const float4 xv = *(const float4*)&h1T[n * HSTR + tx * 4];
            const float4 wv = *(const float4*)&W2s[n * 64 + ty * 4];
            const float xa[4] = {xv.x, xv.y, xv.z, xv.w};
            const float wa[4] = {wv.x, wv.y, wv.z, wv.w};
#pragma unroll
            for (int i = 0; i < 4; i++)
#pragma unroll
                for (int j = 0; j < 4; j++)
                    acc2[i * 4 + j] = fmaf(xa[i], wa[j], acc2[i * 4 + j]);
        }
        __syncthreads();
    }

    // ---- h2 bias + SiLU -> h2T[j][e] ----
#pragma unroll
    for (int j = 0; j < 4; j++) {
        const float bj = b2[ty * 4 + j];
#pragma unroll
        for (int i = 0; i < 4; i++)
            h2T[(ty * 4 + j) * HSTR + tx * 4 + i] = silu_f(acc2[i * 4 + j] + bj);
    }
    // stage W3 [64][128]
#pragma unroll
    for (int i = t; i < 2048; i += 256)
        ((float4*)W3s)[i] = ((const float4*)W3)[i];
    __syncthreads();

    // ---- GEMM3 (64->128): microtile 4e x 8c ----
    float acc3[32];
#pragma unroll
    for (int i = 0; i < 32; i++) acc3[i] = 0.f;
#pragma unroll 16
    for (int k = 0; k < 64; k++) {
        const float4 xv = *(const float4*)&h2T[k * HSTR + tx * 4];
        const float4 w0 = ((const float4*)W3s)[k * 32 + ty * 2];
        const float4 w1 = ((const float4*)W3s)[k * 32 + ty * 2 + 1];
        const float xa[4] = {xv.x, xv.y, xv.z, xv.w};
        const float wa[8] = {w0.x, w0.y, w0.z, w0.w, w1.x, w1.y, w1.z, w1.w};
#pragma unroll
        for (int i = 0; i < 4; i++)
#pragma unroll
            for (int j = 0; j < 8; j++)
                acc3[i * 8 + j] = fmaf(xa[i], wa[j], acc3[i * 8 + j]);
    }

    // ---- bias, store h, local partial sums ----
    float s1 = 0.f, s2 = 0.f;
    float bb[8];
#pragma unroll
    for (int j = 0; j < 8; j++) bb[j] = b3[ty * 8 + j];
#pragma unroll
    for (int i = 0; i < 4; i++) {
        float v[8];
#pragma unroll
        for (int j = 0; j < 8; j++) {
            v[j] = acc3[i * 8 + j] + bb[j];
            s1 += v[j];
            s2 += v[j] * v[j];
        }
        float* dst = &g_h[(size_t)(eb + tx * 4 + i) * NEMB + ty * 8];
        ((float4*)dst)[0] = make_float4(v[0], v[1], v[2], v[3]);
        ((float4*)dst)[1] = make_float4(v[4], v[5], v[6], v[7]);
    }

    // deterministic block tree reduction
    red[t] = s1;
    red[256 + t] = s2;
    __syncthreads();
#pragma unroll
    for (int s = 128; s > 0; s >>= 1) {
        if (t < s) { red[t] += red[t + s]; red[256 + t] += red[256 + t + s]; }
        __syncthreads();
    }
    if (t == 0) {
        g_part[blockIdx.x * 2]     = red[0];
        g_part[blockIdx.x * 2 + 1] = red[256];
    }
}

__global__ void reduce_stats_kernel()
{
    __shared__ double sd[512];
    __shared__ double sq[512];
    const int t = threadIdx.x;  // 512 threads
    double a = 0.0, b = 0.0;
    for (int i = t; i < NBLK; i += 512) {
        a += (double)g_part[2 * i];
        b += (double)g_part[2 * i + 1];
    }
    sd[t] = a; sq[t] = b;
    __syncthreads();
    for (int s = 256; s > 0; s >>= 1) {
        if (t < s) { sd[t] += sd[t + s]; sq[t] += sq[t + s]; }
        __syncthreads();
    }
    if (t == 0) {
        const double cnt  = (double)E_TOT * (double)NEMB;
        const double mean = sd[0] / cnt;
        const double var  = sq[0] / cnt - mean * mean;
        g_stats[0] = (float)mean;
        g_stats[1] = (float)(1.0 / sqrt(var + 1e-5));
    }
}

__global__ void __launch_bounds__(256)
pass2_kernel(const float4* __restrict__ g2x, const float4* __restrict__ lnw,
             const float4* __restrict__ lnb, float4* __restrict__ out)
{
    const float mean = g_stats[0];
    const float rstd = g_stats[1];
    const int i = blockIdx.x * blockDim.x + threadIdx.x;
    const float4 h = ((const float4*)g_h)[i];
    const float4 g = g2x[i];
    const float4 w = lnw[i];
    const float4 b = lnb[i];
    float4 o;
    o.x = fmaf((h.x - mean) * rstd, w.x, g.x + b.x);
    o.y = fmaf((h.y - mean) * rstd, w.y, g.y + b.y);
    o.z = fmaf((h.z - mean) * rstd, w.z, g.z + b.z);
    o.w = fmaf((h.w - mean) * rstd, w.w, g.w + b.w);
    out[i] = o;
}

extern "C" void kernel_launch(void* const* d_in, const int* in_sizes, int n_in,
                              void* d_out, int out_size)
{
    const float* gx     = (const float*)d_in[0];
    const float* mx     = (const float*)d_in[1];
    // d_in[2] me_i, d_in[3] me_x : unused (passthrough in reference)
    const int*   g2me_i = (const int*)d_in[4];
    const float* g2me_x = (const float*)d_in[5];
    // d_in[6] m2ge_i, d_in[7] m2ge_x : unused
    const float* W1 = (const float*)d_in[8];
    const float* b1 = (const float*)d_in[9];
    const float* W2 = (const float*)d_in[10];
    const float* b2 = (const float*)d_in[11];
    const float* W3 = (const float*)d_in[12];
    const float* b3 = (const float*)d_in[13];
    const float* lnw = (const float*)d_in[14];
    const float* lnb = (const float*)d_in[15];
    float* out = (float*)d_out;

    cudaFuncSetAttribute(pass1_kernel,
                         cudaFuncAttributeMaxDynamicSharedMemorySize, SMEM_BYTES);

    pass1_kernel<<<NBLK, 256, SMEM_BYTES>>>(gx, mx, g2me_i, g2me_x,
                                            W1, b1, W2, b2, W3, b3);
    reduce_stats_kernel<<<1, 512>>>();

    const int n4 = (E_TOT * NEMB) / 4;           // 4194304 float4s
    pass2_kernel<<<n4 / 256, 256>>>((const float4*)g2me_x, (const float4*)lnw,
                                    (const float4*)lnb, (float4*)out);
}

// round 3
// speedup vs baseline: 2.5027x; 2.5027x over previous
#include <cuda_runtime.h>
#include <cstdint>
#include <math.h>

#define E_TOT   131072
#define NEMB    128
#define TILE_E  128
#define NBLK    (E_TOT / TILE_E)      // 1024

// smem word offsets
#define O_SA   0            // 16384 words: x tile [128 r x 128 k], tf32, swizzled
#define O_SH   16384        // 16384 words: h1 chunk [128 x 128] / h2 [128 x 64]
#define O_SB   32768        // 8192 words: weight double-buffer (2 x 4096)
#define O_RED  40960        // 512 floats
#define SMEM_BYTES ((40960 + 512) * 4)   // 165888

// device scratch (allocation-free)
__device__ float g_h[(size_t)E_TOT * NEMB];
__device__ float g_part[NBLK * 2];
__device__ float g_stats[2];

__device__ __forceinline__ uint32_t f2tf(float x) {
    uint32_t r;
    asm("cvt.rna.tf32.f32 %0, %1;" : "=r"(r) : "f"(x));
    return r;
}
__device__ __forceinline__ float silu_f(float v) {
    return v * (1.0f / (1.0f + __expf(-v)));
}
__device__ __forceinline__ void mma8(float* d, const uint32_t* a, uint32_t b0, uint32_t b1) {
    asm volatile(
        "mma.sync.aligned.m16n8k8.row.col.f32.tf32.tf32.f32 "
        "{%0,%1,%2,%3}, {%4,%5,%6,%7}, {%8,%9}, {%0,%1,%2,%3};"
        : "+f"(d[0]), "+f"(d[1]), "+f"(d[2]), "+f"(d[3])
        : "r"(a[0]), "r"(a[1]), "r"(a[2]), "r"(a[3]), "r"(b0), "r"(b1));
}

__global__ void __launch_bounds__(256, 1)
fused_mlp_kernel(const float* __restrict__ gx, const float* __restrict__ mx,
                 const int* __restrict__ g2i, const float* __restrict__ g2x,
                 const float* __restrict__ W1, const float* __restrict__ b1,
                 const float* __restrict__ W2, const float* __restrict__ b2,
                 const float* __restrict__ W3, const float* __restrict__ b3)
{
    extern __shared__ uint32_t smu[];
    uint32_t* SA = smu + O_SA;
    uint32_t* SH = smu + O_SH;
    uint32_t* SB = smu + O_SB;
    float*   RED = (float*)(smu + O_RED);

    const int t = threadIdx.x, lane = t & 31, wid = t >> 5;
    const int c4 = lane & 3, r8 = lane >> 2;
    const int mw = wid & 3, nw = wid >> 2;     // 4 m-warps x 2 n-warps
    const int ew = mw * 32;                    // warp edge-row base (32 edges)
    const uint32_t sA = (uint32_t)(r8 << 2);   // A-operand swizzle constant
    const int eb = blockIdx.x * TILE_E;
    const int* __restrict__ rowi = g2i;
    const int* __restrict__ coli = g2i + E_TOT;

    float acc2[2][4][4];
#pragma unroll
    for (int a = 0; a < 2; a++)
#pragma unroll
        for (int b = 0; b < 4; b++)
#pragma unroll
            for (int c = 0; c < 4; c++) acc2[a][b][c] = 0.f;

    for (int nc = 0; nc < 4; nc++) {
        float acc1[2][8][4];
#pragma unroll
        for (int a = 0; a < 2; a++)
#pragma unroll
            for (int b = 0; b < 8; b++)
#pragma unroll
                for (int c = 0; c < 4; c++) acc1[a][b][c] = 0.f;

        for (int src = 0; src < 3; src++) {
            __syncthreads();
            // ---- gather x source tile [128 x 128] -> SA (tf32, swizzled) ----
#pragma unroll 4
            for (int it = 0; it < 16; ++it) {
                const int i = t + it * 256;
                const int e = i >> 5, g4 = i & 31;
                const float* sp;
                if (src == 0)      sp = gx  + (size_t)rowi[eb + e] * 128;
                else if (src == 1) sp = mx  + (size_t)coli[eb + e] * 128;
                else               sp = g2x + (size_t)(eb + e) * 128;
                const float4 v = *(const float4*)(sp + g4 * 4);
                uint32_t* d = SA + e * 128 + (((uint32_t)(4 * g4)) ^ (((uint32_t)e & 7u) << 2));
                d[0] = f2tf(v.x); d[1] = f2tf(v.y); d[2] = f2tf(v.z); d[3] = f2tf(v.w);
            }
            for (int ks = 0; ks < 4; ks++) {
                uint32_t* SBb = SB + (ks & 1) * 4096;
                // ---- stage W1 rows [src*128+ks*32, +32) cols [nc*128, +128) ----
#pragma unroll
                for (int it = 0; it < 4; ++it) {
                    const int i = t + it * 256;
                    const int kr = i >> 5, g4 = i & 31;
                    const float4 v = *(const float4*)(W1 + (size_t)(src * 128 + ks * 32 + kr) * 512
                                                      + nc * 128 + g4 * 4);
                    uint32_t* d = SBb + kr * 128 + (((uint32_t)(4 * g4)) ^ (((uint32_t)kr & 3u) << 3));
                    d[0] = f2tf(v.x); d[1] = f2tf(v.y); d[2] = f2tf(v.z); d[3] = f2tf(v.w);
                }
                __syncthreads();
                const uint32_t* SAr = SA + (ew + r8) * 128;
#pragma unroll
                for (int k8 = 0; k8 < 4; k8++) {
                    const uint32_t cb = ((uint32_t)(ks * 32 + k8 * 8 + c4)) ^ sA;
                    uint32_t a[2][4];
                    a[0][0] = SAr[cb];            a[0][1] = SAr[1024 + cb];
                    a[0][2] = SAr[cb ^ 4u];       a[0][3] = SAr[1024 + (cb ^ 4u)];
                    a[1][0] = SAr[2048 + cb];     a[1][1] = SAr[3072 + cb];
                    a[1][2] = SAr[2048 + (cb ^ 4u)]; a[1][3] = SAr[3072 + (cb ^ 4u)];
                    const uint32_t* Bb = SBb + (k8 * 8 + c4) * 128 + nw * 64 + r8;
#pragma unroll
                    for (int nt = 0; nt < 8; nt++) {
                        const uint32_t b0 = Bb[(nt ^ c4) * 8];
                        const uint32_t b1r = Bb[512 + (nt ^ c4) * 8];
                        mma8(acc1[0][nt], a[0], b0, b1r);
                        mma8(acc1[1][nt], a[1], b0, b1r);
                    }
                }
            }
        }
        // ---- h1 chunk: bias + SiLU -> SH [128 x 128] tf32 swizzled ----
        __syncthreads();
#pragma unroll
        for (int nt = 0; nt < 8; nt++) {
            const float2 bv = *(const float2*)(b1 + nc * 128 + nw * 64 + nt * 8 + c4 * 2);
            const int k = nw * 64 + nt * 8 + c4 * 2;
            const uint32_t wcol = ((uint32_t)k) ^ sA;
#pragma unroll
            for (int mt = 0; mt < 2; mt++)
#pragma unroll
                for (int h = 0; h < 2; h++) {
                    const int r = ew + mt * 16 + h * 8 + r8;
                    uint2 p;
                    p.x = f2tf(silu_f(acc1[mt][nt][h * 2 + 0] + bv.x));
                    p.y = f2tf(silu_f(acc1[mt][nt][h * 2 + 1] + bv.y));
                    *(uint2*)(SH + r * 128 + wcol) = p;
                }
        }
        // ---- GEMM2: h2 += h1c @ W2[nc*128:+128, :] ----
        for (int ks = 0; ks < 4; ks++) {
            uint32_t* SBb = SB + (ks & 1) * 4096;
#pragma unroll
            for (int it = 0; it < 2; ++it) {
                const int i = t + it * 256;
                const int kr = i >> 4, g4 = i & 15;
                const float4 v = *(const float4*)(W2 + (size_t)(nc * 128 + ks * 32 + kr) * 64 + g4 * 4);
                uint32_t* d = SBb + kr * 64 + (((uint32_t)(4 * g4)) ^ (((uint32_t)kr & 3u) << 3));
                d[0] = f2tf(v.x); d[1] = f2tf(v.y); d[2] = f2tf(v.z); d[3] = f2tf(v.w);
            }
            __syncthreads();
            const uint32_t* SHr = SH + (ew + r8) * 128;
#pragma unroll
            for (int k8 = 0; k8 < 4; k8++) {
                const uint32_t cb = ((uint32_t)(ks * 32 + k8 * 8 + c4)) ^ sA;
                uint32_t a[2][4];
                a[0][0] = SHr[cb];            a[0][1] = SHr[1024 + cb];
                a[0][2] = SHr[cb ^ 4u];       a[0][3] = SHr[1024 + (cb ^ 4u)];
                a[1][0] = SHr[2048 + cb];     a[1][1] = SHr[3072 + cb];
                a[1][2] = SHr[2048 + (cb ^ 4u)]; a[1][3] = SHr[3072 + (cb ^ 4u)];
                const uint32_t* Bb = SBb + (k8 * 8 + c4) * 64 + nw * 32 + r8;
#pragma unroll
                for (int nt = 0; nt < 4; nt++) {
                    const uint32_t b0 = Bb[(nt ^ c4) * 8];
                    const uint32_t b1r = Bb[256 + (nt ^ c4) * 8];
                    mma8(acc2[0][nt], a[0], b0, b1r);
                    mma8(acc2[1][nt], a[1], b0, b1r);
                }
            }
        }
    }

    // ---- h2: bias + SiLU -> SH [128 x 64] tf32 swizzled ----
    __syncthreads();
#pragma unroll
    for (int nt = 0; nt < 4; nt++) {
        const float2 bv = *(const float2*)(b2 + nw * 32 + nt * 8 + c4 * 2);
        const int k = nw * 32 + nt * 8 + c4 * 2;
        const uint32_t wcol = ((uint32_t)k) ^ sA;
#pragma unroll
        for (int mt = 0; mt < 2; mt++)
#pragma unroll
            for (int h = 0; h < 2; h++) {
                const int r = ew + mt * 16 + h * 8 + r8;
                uint2 p;
                p.x = f2tf(silu_f(acc2[mt][nt][h * 2 + 0] + bv.x));
                p.y = f2tf(silu_f(acc2[mt][nt][h * 2 + 1] + bv.y));
                *(uint2*)(SH + r * 64 + wcol) = p;
            }
    }
    // ---- stage W3 [64 x 128] into SB (contiguous 8192 words) ----
#pragma unroll
    for (int it = 0; it < 8; ++it) {
        const int i = t + it * 256;
        const int kr = i >> 5, g4 = i & 31;
        const float4 v = *(const float4*)(W3 + (size_t)kr * 128 + g4 * 4);
        uint32_t* d = SB + kr * 128 + (((uint32_t)(4 * g4)) ^ (((uint32_t)kr & 3u) << 3));
        d[0] = f2tf(v.x); d[1] = f2tf(v.y); d[2] = f2tf(v.z); d[3] = f2tf(v.w);
    }
    __syncthreads();

    // ---- GEMM3: out = h2 @ W3 ----
    float acc3[2][8][4];
#pragma unroll
    for (int a = 0; a < 2; a++)
#pragma unroll
        for (int b = 0; b < 8; b++)
#pragma unroll
            for (int c = 0; c < 4; c++) acc3[a][b][c] = 0.f;

    {
        const uint32_t* SHr = SH + (ew + r8) * 64;
#pragma unroll
        for (int k8 = 0; k8 < 8; k8++) {
            const uint32_t cb = ((uint32_t)(k8 * 8 + c4)) ^ sA;
            uint32_t a[2][4];
            a[0][0] = SHr[cb];           a[0][1] = SHr[512 + cb];
            a[0][2] = SHr[cb ^ 4u];      a[0][3] = SHr[512 + (cb ^ 4u)];
            a[1][0] = SHr[1024 + cb];    a[1][1] = SHr[1536 + cb];
            a[1][2] = SHr[1024 + (cb ^ 4u)]; a[1][3] = SHr[1536 + (cb ^ 4u)];
            const uint32_t* Bb = SB + (k8 * 8 + c4) * 128 + nw * 64 + r8;
#pragma unroll
            for (int nt = 0; nt < 8; nt++) {
                const uint32_t b0 = Bb[(nt ^ c4) * 8];
                const uint32_t b1r = Bb[512 + (nt ^ c4) * 8];
                mma8(acc3[0][nt], a[0], b0, b1r);
                mma8(acc3[1][nt], a[1], b0, b1r);
            }
        }
    }

    // ---- epilogue: bias, partial sums, store h ----
    float s1 = 0.f, s2 = 0.f;
#pragma unroll
    for (int nt = 0; nt < 8; nt++) {
        const int col = nw * 64 + nt * 8 + c4 * 2;
        const float2 bv = *(const float2*)(b3 + col);
#pragma unroll
        for (int mt = 0; mt < 2; mt++)
#pragma unroll
            for (int h = 0; h < 2; h++) {
                const int r = ew + mt * 16 + h * 8 + r8;
                float2 v;
                v.x = acc3[mt][nt][h * 2 + 0] + bv.x;
                v.y = acc3[mt][nt][h * 2 + 1] + bv.y;
                s1 += v.x + v.y;
                s2 += v.x * v.x + v.y * v.y;
                *(float2*)(g_h + (size_t)(eb + r) * NEMB + col) = v;
            }
    }
    RED[t] = s1; RED[256 + t] = s2;
    __syncthreads();
#pragma unroll
    for (int s = 128; s > 0; s >>= 1) {
        if (t < s) { RED[t] += RED[t + s]; RED[256 + t] += RED[256 + t + s]; }
        __syncthreads();
    }
    if (t == 0) {
        g_part[blockIdx.x * 2]     = RED[0];
        g_part[blockIdx.x * 2 + 1] = RED[256];
    }
}

__global__ void reduce_stats_kernel()
{
    __shared__ double sd[512];
    __shared__ double sq[512];
    const int t = threadIdx.x;
    double a = 0.0, b = 0.0;
    for (int i = t; i < NBLK; i += 512) {
        a += (double)g_part[2 * i];
        b += (double)g_part[2 * i + 1];
    }
    sd[t] = a; sq[t] = b;
    __syncthreads();
    for (int s = 256; s > 0; s >>= 1) {
        if (t < s) { sd[t] += sd[t + s]; sq[t] += sq[t + s]; }
        __syncthreads();
    }
    if (t == 0) {
        const double cnt  = (double)E_TOT * (double)NEMB;
        const double mean = sd[0] / cnt;
        const double var  = sq[0] / cnt - mean * mean;
        g_stats[0] = (float)mean;
        g_stats[1] = (float)(1.0 / sqrt(var + 1e-5));
    }
}

__global__ void __launch_bounds__(256)
pass2_kernel(const float4* __restrict__ g2x, const float4* __restrict__ lnw,
             const float4* __restrict__ lnb, float4* __restrict__ out)
{
    const float mean = g_stats[0];
    const float rstd = g_stats[1];
    const int i = blockIdx.x * blockDim.x + threadIdx.x;
    const float4 h = ((const float4*)g_h)[i];
    const float4 g = g2x[i];
    const float4 w = lnw[i];
    const float4 b = lnb[i];
    float4 o;
    o.x = fmaf((h.x - mean) * rstd, w.x, g.x + b.x);
    o.y = fmaf((h.y - mean) * rstd, w.y, g.y + b.y);
    o.z = fmaf((h.z - mean) * rstd, w.z, g.z + b.z);
    o.w = fmaf((h.w - mean) * rstd, w.w, g.w + b.w);
    out[i] = o;
}

extern "C" void kernel_launch(void* const* d_in, const int* in_sizes, int n_in,
                              void* d_out, int out_size)
{
    const float* gx     = (const float*)d_in[0];
    const float* mx     = (const float*)d_in[1];
    const int*   g2me_i = (const int*)d_in[4];
    const float* g2me_x = (const float*)d_in[5];
    const float* W1 = (const float*)d_in[8];
    const float* b1 = (const float*)d_in[9];
    const float* W2 = (const float*)d_in[10];
    const float* b2 = (const float*)d_in[11];
    const float* W3 = (const float*)d_in[12];
    const float* b3 = (const float*)d_in[13];
    const float* lnw = (const float*)d_in[14];
    const float* lnb = (const float*)d_in[15];
    float* out = (float*)d_out;

    cudaFuncSetAttribute(fused_mlp_kernel,
                         cudaFuncAttributeMaxDynamicSharedMemorySize, SMEM_BYTES);

    fused_mlp_kernel<<<NBLK, 256, SMEM_BYTES>>>(gx, mx, g2me_i, g2me_x,
                                                W1, b1, W2, b2, W3, b3);
    reduce_stats_kernel<<<1, 512>>>();

    const int n4 = (E_TOT * NEMB) / 4;
    pass2_kernel<<<n4 / 256, 256>>>((const float4*)g2me_x, (const float4*)lnw,
                                    (const float4*)lnb, (float4*)out);
}

// round 4
// speedup vs baseline: 3.3678x; 1.3457x over previous
#include <cuda_runtime.h>
#include <cstdint>
#include <math.h>

#define E_TOT   131072
#define NEMB    128
#define TILE_E  128
#define NBLK    (E_TOT / TILE_E)      // 1024
#define NTHR    512

// smem word offsets
#define O_SA   0            // 32768 words: [128 e][256 k] gx|mx tf32 swizzled
#define O_SH   32768        // 16384 words: g2x tile / h1 chunk / h2
#define O_SB   49152        // 8192 words: weight double-buffer (2 x 4096)
#define SMEM_BYTES ((49152 + 8192) * 4)   // 229376

__device__ float g_h[(size_t)E_TOT * NEMB];
__device__ float g_part[NBLK * 2];
__device__ float g_stats[2];

__device__ __forceinline__ uint32_t f2tf(float x) {
    uint32_t r;
    asm("cvt.rna.tf32.f32 %0, %1;" : "=r"(r) : "f"(x));
    return r;
}
__device__ __forceinline__ float silu_f(float v) {
    return v * (1.0f / (1.0f + __expf(-v)));
}
__device__ __forceinline__ void mma8(float* d, const uint32_t* a, uint32_t b0, uint32_t b1) {
    asm volatile(
        "mma.sync.aligned.m16n8k8.row.col.f32.tf32.tf32.f32 "
        "{%0,%1,%2,%3}, {%4,%5,%6,%7}, {%8,%9}, {%0,%1,%2,%3};"
        : "+f"(d[0]), "+f"(d[1]), "+f"(d[2]), "+f"(d[3])
        : "r"(a[0]), "r"(a[1]), "r"(a[2]), "r"(a[3]), "r"(b0), "r"(b1));
}
__device__ __forceinline__ void sts_tf4(uint32_t* d, float4 v) {
    d[0] = f2tf(v.x); d[1] = f2tf(v.y); d[2] = f2tf(v.z); d[3] = f2tf(v.w);
}

__global__ void __launch_bounds__(NTHR, 1)
fused_mlp_kernel(const float* __restrict__ gx, const float* __restrict__ mx,
                 const int* __restrict__ g2i, const float* __restrict__ g2x,
                 const float* __restrict__ W1, const float* __restrict__ b1,
                 const float* __restrict__ W2, const float* __restrict__ b2,
                 const float* __restrict__ W3, const float* __restrict__ b3)
{
    extern __shared__ uint32_t smu[];
    uint32_t* SA = smu + O_SA;
    uint32_t* SH = smu + O_SH;
    uint32_t* SB = smu + O_SB;

    const int t = threadIdx.x, lane = t & 31, wid = t >> 5;
    const int c4 = lane & 3, r8 = lane >> 2;
    const int mw = wid & 3, nw = wid >> 2;     // 4 m-warps x 4 n-warps
    const int ew = mw * 32;
    const uint32_t sA = (uint32_t)(r8 << 2);
    const uint32_t bxor = (uint32_t)(c4 << 3);
    const int eb = blockIdx.x * TILE_E;
    const int* __restrict__ rowi = g2i;
    const int* __restrict__ coli = g2i + E_TOT;

    // ---- one-time gather: gx | mx -> SA [128][256] ----
#pragma unroll
    for (int it = 0; it < 8; ++it) {
        const int i = t + it * NTHR;
        const int e = i >> 5, g4 = i & 31;
        const float4 v = *(const float4*)(gx + (size_t)rowi[eb + e] * 128 + g4 * 4);
        sts_tf4(SA + e * 256 + ((uint32_t)(4 * g4) ^ (((uint32_t)e & 7u) << 2)), v);
    }
#pragma unroll
    for (int it = 0; it < 8; ++it) {
        const int i = t + it * NTHR;
        const int e = i >> 5, g4 = i & 31;
        const float4 v = *(const float4*)(mx + (size_t)coli[eb + e] * 128 + g4 * 4);
        sts_tf4(SA + e * 256 + 128 + ((uint32_t)(4 * g4) ^ (((uint32_t)e & 7u) << 2)), v);
    }

    float acc2[2][2][4];
#pragma unroll
    for (int a = 0; a < 2; a++)
#pragma unroll
        for (int b = 0; b < 2; b++)
#pragma unroll
            for (int c = 0; c < 4; c++) acc2[a][b][c] = 0.f;

    const int kr1 = t >> 5;          // W1 stage row (it-dependent below)
    const int g41 = t & 31;

    for (int nc = 0; nc < 4; nc++) {
        __syncthreads();   // SH readers (prev GEMM2) done
        // ---- stage g2x tile -> SH [128][128] ----
#pragma unroll
        for (int it = 0; it < 8; ++it) {
            const int i = t + it * NTHR;
            const int e = i >> 5, g4 = i & 31;
            const float4 v = *(const float4*)(g2x + (size_t)(eb + e) * 128 + g4 * 4);
            sts_tf4(SH + e * 128 + ((uint32_t)(4 * g4) ^ (((uint32_t)e & 7u) << 2)), v);
        }

        float acc1[2][4][4];
#pragma unroll
        for (int a = 0; a < 2; a++)
#pragma unroll
            for (int b = 0; b < 4; b++)
#pragma unroll
                for (int c = 0; c < 4; c++) acc1[a][b][c] = 0.f;

        // prologue: load W1 stage 0
        float4 wa = *(const float4*)(W1 + (size_t)(kr1) * 512 + nc * 128 + g41 * 4);
        float4 wb = *(const float4*)(W1 + (size_t)(16 + kr1) * 512 + nc * 128 + g41 * 4);

        for (int s = 0; s < 12; s++) {
            uint32_t* SBb = SB + (s & 1) * 4096;
            sts_tf4(SBb + kr1 * 128 + ((uint32_t)(4 * g41) ^ (((uint32_t)kr1 & 3u) << 3)), wa);
            sts_tf4(SBb + (16 + kr1) * 128 + ((uint32_t)(4 * g41) ^ ((((uint32_t)kr1 + 16u) & 3u) << 3)), wb);
            if (s < 11) {
                wa = *(const float4*)(W1 + (size_t)((s + 1) * 32 + kr1) * 512 + nc * 128 + g41 * 4);
                wb = *(const float4*)(W1 + (size_t)((s + 1) * 32 + 16 + kr1) * 512 + nc * 128 + g41 * 4);
            }
            __syncthreads();
            const int src = s >> 2;
#pragma unroll
            for (int k8 = 0; k8 < 4; k8++) {
                uint32_t a[2][4];
                if (src < 2) {
                    const uint32_t* SAr = SA + (ew + r8) * 256;
                    const uint32_t cb = ((uint32_t)(src * 128 + (s & 3) * 32 + k8 * 8 + c4)) ^ sA;
                    a[0][0] = SAr[cb];          a[0][1] = SAr[2048 + cb];
                    a[0][2] = SAr[cb ^ 4u];     a[0][3] = SAr[2048 + (cb ^ 4u)];
                    a[1][0] = SAr[4096 + cb];   a[1][1] = SAr[6144 + cb];
                    a[1][2] = SAr[4096 + (cb ^ 4u)]; a[1][3] = SAr[6144 + (cb ^ 4u)];
                } else {
                    const uint32_t* SHr = SH + (ew + r8) * 128;
                    const uint32_t cb = ((uint32_t)((s & 3) * 32 + k8 * 8 + c4)) ^ sA;
                    a[0][0] = SHr[cb];          a[0][1] = SHr[1024 + cb];
                    a[0][2] = SHr[cb ^ 4u];     a[0][3] = SHr[1024 + (cb ^ 4u)];
                    a[1][0] = SHr[2048 + cb];   a[1][1] = SHr[3072 + cb];
                    a[1][2] = SHr[2048 + (cb ^ 4u)]; a[1][3] = SHr[3072 + (cb ^ 4u)];
                }
                const uint32_t* base = SBb + (k8 * 8 + c4) * 128;
#pragma unroll
                for (int nt = 0; nt < 4; nt++) {
                    const uint32_t wc = ((uint32_t)(nw * 32 + nt * 8 + r8)) ^ bxor;
                    const uint32_t b0 = base[wc];
                    const uint32_t b1r = base[512 + wc];
                    mma8(acc1[0][nt], a[0], b0, b1r);
                    mma8(acc1[1][nt], a[1], b0, b1r);
                }
            }
        }
        __syncthreads();   // all src2 SH reads done; SB reads done
        // ---- h1: bias + SiLU -> SH [128][128] ----
#pragma unroll
        for (int nt = 0; nt < 4; nt++) {
            const int k = nw * 32 + nt * 8 + c4 * 2;
            const float2 bv = *(const float2*)(b1 + nc * 128 + k);
            const uint32_t wcol = ((uint32_t)k) ^ sA;
#pragma unroll
            for (int mt = 0; mt < 2; mt++)
#pragma unroll
                for (int h = 0; h < 2; h++) {
                    const int r = ew + mt * 16 + h * 8 + r8;
                    uint2 p;
                    p.x = f2tf(silu_f(acc1[mt][nt][h * 2 + 0] + bv.x));
                    p.y = f2tf(silu_f(acc1[mt][nt][h * 2 + 1] + bv.y));
                    *(uint2*)(SH + r * 128 + wcol) = p;
                }
        }
        // ---- GEMM2: h2 += h1c @ W2 chunk (pipelined stages of 32 rows) ----
        const int kr2 = t >> 4, g42 = t & 15;
        float4 w2r = *(const float4*)(W2 + (size_t)(nc * 128 + kr2) * 64 + g42 * 4);
        for (int s2 = 0; s2 < 4; s2++) {
            uint32_t* SBb = SB + (s2 & 1) * 4096;
            sts_tf4(SBb + kr2 * 64 + ((uint32_t)(4 * g42) ^ (((uint32_t)kr2 & 3u) << 3)), w2r);
            if (s2 < 3)
                w2r = *(const float4*)(W2 + (size_t)(nc * 128 + (s2 + 1) * 32 + kr2) * 64 + g42 * 4);
            __syncthreads();
#pragma unroll
            for (int k8 = 0; k8 < 4; k8++) {
                const uint32_t* SHr = SH + (ew + r8) * 128;
                const uint32_t cb = ((uint32_t)(s2 * 32 + k8 * 8 + c4)) ^ sA;
                uint32_t a[2][4];
                a[0][0] = SHr[cb];          a[0][1] = SHr[1024 + cb];
                a[0][2] = SHr[cb ^ 4u];     a[0][3] = SHr[1024 + (cb ^ 4u)];
                a[1][0] = SHr[2048 + cb];   a[1][1] = SHr[3072 + cb];
                a[1][2] = SHr[2048 + (cb ^ 4u)]; a[1][3] = SHr[3072 + (cb ^ 4u)];
                const uint32_t* base = SBb + (k8 * 8 + c4) * 64;
#pragma unroll
                for (int nt = 0; nt < 2; nt++) {
                    const uint32_t wc = ((uint32_t)(nw * 16 + nt * 8 + r8)) ^ bxor;
                    const uint32_t b0 = base[wc];
                    const uint32_t b1r = base[256 + wc];
                    mma8(acc2[0][nt], a[0], b0, b1r);
                    mma8(acc2[1][nt], a[1], b0, b1r);
                }
            }
        }
    }
    __syncthreads();   // GEMM2 SH reads done
    // ---- h2: bias + SiLU -> SH [128][64] ----
#pragma unroll
    for (int nt = 0; nt < 2; nt++) {
        const int k = nw * 16 + nt * 8 + c4 * 2;
        const float2 bv = *(const float2*)(b2 + k);
        const uint32_t wcol = ((uint32_t)k) ^ sA;
#pragma unroll
        for (int mt = 0; mt < 2; mt++)
#pragma unroll
            for (int h = 0; h < 2; h++) {
                const int r = ew + mt * 16 + h * 8 + r8;
                uint2 p;
                p.x = f2tf(silu_f(acc2[mt][nt][h * 2 + 0] + bv.x));
                p.y = f2tf(silu_f(acc2[mt][nt][h * 2 + 1] + bv.y));
                *(uint2*)(SH + r * 64 + wcol) = p;
            }
    }
    // ---- stage W3 [64][128] -> SB ----
#pragma unroll
    for (int it = 0; it < 4; ++it) {
        const int i = t + it * NTHR;
        const int kr = i >> 5, g4 = i & 31;
        const float4 v = *(const float4*)(W3 + (size_t)kr * 128 + g4 * 4);
        sts_tf4(SB + kr * 128 + ((uint32_t)(4 * g4) ^ (((uint32_t)kr & 3u) << 3)), v);
    }
    __syncthreads();

    // ---- GEMM3 ----
    float acc3[2][4][4];
#pragma unroll
    for (int a = 0; a < 2; a++)
#pragma unroll
        for (int b = 0; b < 4; b++)
#pragma unroll
            for (int c = 0; c < 4; c++) acc3[a][b][c] = 0.f;
    {
        const uint32_t* SHr = SH + (ew + r8) * 64;
#pragma unroll
        for (int k8 = 0; k8 < 8; k8++) {
            const uint32_t cb = ((uint32_t)(k8 * 8 + c4)) ^ sA;
            uint32_t a[2][4];
            a[0][0] = SHr[cb];          a[0][1] = SHr[512 + cb];
            a[0][2] = SHr[cb ^ 4u];     a[0][3] = SHr[512 + (cb ^ 4u)];
            a[1][0] = SHr[1024 + cb];   a[1][1] = SHr[1536 + cb];
            a[1][2] = SHr[1024 + (cb ^ 4u)]; a[1][3] = SHr[1536 + (cb ^ 4u)];
            const uint32_t* base = SB + (k8 * 8 + c4) * 128;
#pragma unroll
            for (int nt = 0; nt < 4; nt++) {
                const uint32_t wc = ((uint32_t)(nw * 32 + nt * 8 + r8)) ^ bxor;
                const uint32_t b0 = base[wc];
                const uint32_t b1r = base[512 + wc];
                mma8(acc3[0][nt], a[0], b0, b1r);
                mma8(acc3[1][nt], a[1], b0, b1r);
            }
        }
    }

    // ---- epilogue: bias, partial sums, store h ----
    float s1 = 0.f, s2s = 0.f;
#pragma unroll
    for (int nt = 0; nt < 4; nt++) {
        const int col = nw * 32 + nt * 8 + c4 * 2;
        const float2 bv = *(const float2*)(b3 + col);
#pragma unroll
        for (int mt = 0; mt < 2; mt++)
#pragma unroll
            for (int h = 0; h < 2; h++) {
                const int r = ew + mt * 16 + h * 8 + r8;
                float2 v;
                v.x = acc3[mt][nt][h * 2 + 0] + bv.x;
                v.y = acc3[mt][nt][h * 2 + 1] + bv.y;
                s1  += v.x + v.y;
                s2s += v.x * v.x + v.y * v.y;
                *(float2*)(g_h + (size_t)(eb + r) * NEMB + col) = v;
            }
    }
    float* RED = (float*)smu;   // alias SA (dead)
    __syncthreads();
    RED[t] = s1; RED[NTHR + t] = s2s;
    __syncthreads();
#pragma unroll
    for (int s = NTHR / 2; s > 0; s >>= 1) {
        if (t < s) { RED[t] += RED[t + s]; RED[NTHR + t] += RED[NTHR + t + s]; }
        __syncthreads();
    }
    if (t == 0) {
        g_part[blockIdx.x * 2]     = RED[0];
        g_part[blockIdx.x * 2 + 1] = RED[NTHR];
    }
}

__global__ void reduce_stats_kernel()
{
    __shared__ double sd[512];
    __shared__ double sq[512];
    const int t = threadIdx.x;
    double a = 0.0, b = 0.0;
    for (int i = t; i < NBLK; i += 512) {
        a += (double)g_part[2 * i];
        b += (double)g_part[2 * i + 1];
    }
    sd[t] = a; sq[t] = b;
    __syncthreads();
    for (int s = 256; s > 0; s >>= 1) {
        if (t < s) { sd[t] += sd[t + s]; sq[t] += sq[t + s]; }
        __syncthreads();
    }
    if (t == 0) {
        const double cnt  = (double)E_TOT * (double)NEMB;
        const double mean = sd[0] / cnt;
        const double var  = sq[0] / cnt - mean * mean;
        g_stats[0] = (float)mean;
        g_stats[1] = (float)(1.0 / sqrt(var + 1e-5));
    }
}

__global__ void __launch_bounds__(256)
pass2_kernel(const float4* __restrict__ g2x, const float4* __restrict__ lnw,
             const float4* __restrict__ lnb, float4* __restrict__ out)
{
    const float mean = g_stats[0];
    const float rstd = g_stats[1];
    const int i = blockIdx.x * blockDim.x + threadIdx.x;
    const float4 h = ((const float4*)g_h)[i];
    const float4 g = g2x[i];
    const float4 w = lnw[i];
    const float4 b = lnb[i];
    float4 o;
    o.x = fmaf((h.x - mean) * rstd, w.x, g.x + b.x);
    o.y = fmaf((h.y - mean) * rstd, w.y, g.y + b.y);
    o.z = fmaf((h.z - mean) * rstd, w.z, g.z + b.z);
    o.w = fmaf((h.w - mean) * rstd, w.w, g.w + b.w);
    out[i] = o;
}

extern "C" void kernel_launch(void* const* d_in, const int* in_sizes, int n_in,
                              void* d_out, int out_size)
{
    const float* gx     = (const float*)d_in[0];
    const float* mx     = (const float*)d_in[1];
    const int*   g2me_i = (const int*)d_in[4];
    const float* g2me_x = (const float*)d_in[5];
    const float* W1 = (const float*)d_in[8];
    const float* b1 = (const float*)d_in[9];
    const float* W2 = (const float*)d_in[10];
    const float* b2 = (const float*)d_in[11];
    const float* W3 = (const float*)d_in[12];
    const float* b3 = (const float*)d_in[13];
    const float* lnw = (const float*)d_in[14];
    const float* lnb = (const float*)d_in[15];
    float* out = (float*)d_out;

    cudaFuncSetAttribute(fused_mlp_kernel,
                         cudaFuncAttributeMaxDynamicSharedMemorySize, SMEM_BYTES);

    fused_mlp_kernel<<<NBLK, NTHR, SMEM_BYTES>>>(gx, mx, g2me_i, g2me_x,
                                                 W1, b1, W2, b2, W3, b3);
    reduce_stats_kernel<<<1, 512>>>();

    const int n4 = (E_TOT * NEMB) / 4;
    pass2_kernel<<<n4 / 256, 256>>>((const float4*)g2me_x, (const float4*)lnw,
                                    (const float4*)lnb, (float4*)out);
}

// round 6
// speedup vs baseline: 3.6518x; 1.0843x over previous
#include <cuda_runtime.h>
#include <cstdint>
#include <math.h>

#define E_TOT   131072
#define NEMB    128
#define TILE_E  128
#define NBLK    (E_TOT / TILE_E)      // 1024
#define NTHR    512

// smem word offsets
#define O_SA   0            // 32768 words: [128 e][256 k] gx|mx f32 swizzled
#define O_SH   32768        // 16384 words: g2x tile / h1 chunk / h2
#define O_SB   49152        // 8192 words: weight double-buffer (2 x 4096)
#define SMEM_BYTES ((49152 + 8192) * 4)   // 229376

__device__ uint32_t g_W1f[196608];   // [nc(4)][stage(12)][k8(4)][ntp(8)][lane(32)][4]
__device__ uint32_t g_W2f[32768];    // [nc(4)][stage(4)][k8(4)][ntp(4)][lane(32)][4]
__device__ uint32_t g_W3f[8192];     // [stage(4)][k8l(2)][ntp(8)][lane(32)][4]
__device__ float g_h[(size_t)E_TOT * NEMB];
__device__ float g_part[NBLK * 2];
__device__ float g_stats[2];

__device__ __forceinline__ uint32_t f2tf(float x) {
    uint32_t r;
    asm("cvt.rna.tf32.f32 %0, %1;" : "=r"(r) : "f"(x));
    return r;
}
__device__ __forceinline__ float silu_f(float v) {
    return v * (1.0f / (1.0f + __expf(-v)));
}
__device__ __forceinline__ void mma8(float* d, const uint32_t* a, uint32_t b0, uint32_t b1) {
    asm volatile(
        "mma.sync.aligned.m16n8k8.row.col.f32.tf32.tf32.f32 "
        "{%0,%1,%2,%3}, {%4,%5,%6,%7}, {%8,%9}, {%0,%1,%2,%3};"
        : "+f"(d[0]), "+f"(d[1]), "+f"(d[2]), "+f"(d[3])
        : "r"(a[0]), "r"(a[1]), "r"(a[2]), "r"(a[3]), "r"(b0), "r"(b1));
}

// ---- prologue: weights -> tf32, B-fragment-major images ----
// fragment word w: (w&1) selects b0/b1 (k += 4*(w&1)); (w>>1) selects n-tile of pair.
// per-lane: k = base + (lane&3) [+4], n = ntile*8 + (lane>>2)
__global__ void prep_w_kernel(const float* __restrict__ W1,
                              const float* __restrict__ W2,
                              const float* __restrict__ W3)
{
    const int i0 = blockIdx.x * blockDim.x + threadIdx.x;
    const int str = gridDim.x * blockDim.x;
    for (int i = i0; i < 196608; i += str) {
        const int nc = i / 49152, r = i % 49152;
        const int s = r / 4096, r2 = r % 4096;
        const int k8 = r2 >> 10, ntp = (r2 >> 7) & 7, l = (r2 >> 2) & 31, w = r2 & 3;
        const int k = s * 32 + k8 * 8 + (l & 3) + (w & 1) * 4;
        const int n = nc * 128 + (ntp * 2 + (w >> 1)) * 8 + (l >> 2);
        g_W1f[i] = f2tf(W1[k * 512 + n]);
    }
    for (int i = i0; i < 32768; i += str) {
        const int nc = i / 8192, r = i % 8192;
        const int s = r / 2048, r2 = r % 2048;
        const int k8 = r2 >> 9, ntp = (r2 >> 7) & 3, l = (r2 >> 2) & 31, w = r2 & 3;
        const int k = nc * 128 + s * 32 + k8 * 8 + (l & 3) + (w & 1) * 4;
        const int n = (ntp * 2 + (w >> 1)) * 8 + (l >> 2);
        g_W2f[i] = f2tf(W2[k * 64 + n]);
    }
    for (int i = i0; i < 8192; i += str) {
        const int s = i / 2048, r2 = i % 2048;
        const int k8l = r2 >> 10, ntp = (r2 >> 7) & 7, l = (r2 >> 2) & 31, w = r2 & 3;
        const int k = s * 16 + k8l * 8 + (l & 3) + (w & 1) * 4;
        const int n = (ntp * 2 + (w >> 1)) * 8 + (l >> 2);
        g_W3f[i] = f2tf(W3[k * 128 + n]);
    }
}

__global__ void __launch_bounds__(NTHR, 1)
fused_mlp_kernel(const float* __restrict__ gx, const float* __restrict__ mx,
                 const int* __restrict__ g2i, const float* __restrict__ g2x,
                 const float* __restrict__ b1, const float* __restrict__ b2,
                 const float* __restrict__ b3)
{
    extern __shared__ uint32_t smu[];
    uint32_t* SA = smu + O_SA;
    uint32_t* SH = smu + O_SH;
    uint32_t* SB = smu + O_SB;
    float* SAf = (float*)SA;
    float* SHf = (float*)SH;

    const int t = threadIdx.x, lane = t & 31, wid = t >> 5;
    const int c4 = lane & 3, r8 = lane >> 2;
    const int mw = wid & 3, nw = wid >> 2;     // 4 m-warps x 4 n-warps
    const int ew = mw * 32;
    const uint32_t sA = (uint32_t)(r8 << 2);
    const int eb = blockIdx.x * TILE_E;
    const int* __restrict__ rowi = g2i;
    const int* __restrict__ coli = g2i + E_TOT;

    const float4* W1f4 = (const float4*)g_W1f;
    const float4* W2f4 = (const float4*)g_W2f;
    const float4* W3f4 = (const float4*)g_W3f;

    // ---- one-time gather: gx | mx -> SA [128][256] (raw f32, XOR swizzled) ----
#pragma unroll
    for (int it = 0; it < 8; ++it) {
        const int i = t + it * NTHR;
        const int e = i >> 5, g4 = i & 31;
        const float4 v = *(const float4*)(gx + (size_t)rowi[eb + e] * 128 + g4 * 4);
        *(float4*)(SAf + e * 256 + ((4u * g4) ^ (((uint32_t)e & 7u) << 2))) = v;
    }
#pragma unroll
    for (int it = 0; it < 8; ++it) {
        const int i = t + it * NTHR;
        const int e = i >> 5, g4 = i & 31;
        const float4 v = *(const float4*)(mx + (size_t)coli[eb + e] * 128 + g4 * 4);
        *(float4*)(SAf + e * 256 + 128 + ((4u * g4) ^ (((uint32_t)e & 7u) << 2))) = v;
    }

    float acc2[2][2][4];
#pragma unroll
    for (int a = 0; a < 2; a++)
#pragma unroll
        for (int b = 0; b < 2; b++)
#pragma unroll
            for (int c = 0; c < 4; c++) acc2[a][b][c] = 0.f;

    for (int nc = 0; nc < 4; nc++) {
        __syncthreads();   // prev GEMM2 SH reads done
        // ---- stage g2x tile -> SH [128][128] ----
#pragma unroll
        for (int it = 0; it < 8; ++it) {
            const int i = t + it * NTHR;
            const int e = i >> 5, g4 = i & 31;
            const float4 v = *(const float4*)(g2x + (size_t)(eb + e) * 128 + g4 * 4);
            *(float4*)(SHf + e * 128 + ((4u * g4) ^ (((uint32_t)e & 7u) << 2))) = v;
        }

        float acc1[2][4][4];
#pragma unroll
        for (int a = 0; a < 2; a++)
#pragma unroll
            for (int b = 0; b < 4; b++)
#pragma unroll
                for (int c = 0; c < 4; c++) acc1[a][b][c] = 0.f;

        // prologue: load W1 stage 0 image
        float4 w0 = W1f4[(size_t)(nc * 12) * 1024 + t];
        float4 w1 = W1f4[(size_t)(nc * 12) * 1024 + 512 + t];

        for (int s = 0; s < 12; s++) {
            float4* SBb4 = (float4*)(SB + (s & 1) * 4096);
            SBb4[t] = w0;
            SBb4[512 + t] = w1;
            if (s < 11) {
                w0 = W1f4[(size_t)(nc * 12 + s + 1) * 1024 + t];
                w1 = W1f4[(size_t)(nc * 12 + s + 1) * 1024 + 512 + t];
            }
            __syncthreads();
            const uint32_t* SBb = SB + (s & 1) * 4096;
            const int kb = s * 32;
#pragma unroll
            for (int k8 = 0; k8 < 4; k8++) {
                uint32_t a[2][4];
                if (s < 8) {
                    const uint32_t* SAr = SA + (ew + r8) * 256;
                    const uint32_t cb = ((uint32_t)(kb + k8 * 8 + c4)) ^ sA;
                    a[0][0] = SAr[cb];            a[0][1] = SAr[2048 + cb];
                    a[0][2] = SAr[cb ^ 4u];       a[0][3] = SAr[2048 + (cb ^ 4u)];
                    a[1][0] = SAr[4096 + cb];     a[1][1] = SAr[6144 + cb];
                    a[1][2] = SAr[4096 + (cb ^ 4u)]; a[1][3] = SAr[6144 + (cb ^ 4u)];
                } else {
                    const uint32_t* SHr = SH + (ew + r8) * 128;
                    const uint32_t cb = ((uint32_t)(kb - 256 + k8 * 8 + c4)) ^ sA;
                    a[0][0] = SHr[cb];            a[0][1] = SHr[1024 + cb];
                    a[0][2] = SHr[cb ^ 4u];       a[0][3] = SHr[1024 + (cb ^ 4u)];
                    a[1][0] = SHr[2048 + cb];     a[1][1] = SHr[3072 + cb];
                    a[1][2] = SHr[2048 + (cb ^ 4u)]; a[1][3] = SHr[3072 + (cb ^ 4u)];
                }
                const uint4* Bb = (const uint4*)(SBb + k8 * 1024 + nw * 256) + lane;
                const uint4 f0 = Bb[0];
                const uint4 f1 = Bb[32];
                mma8(acc1[0][0], a[0], f0.x, f0.y);
                mma8(acc1[1][0], a[1], f0.x, f0.y);
                mma8(acc1[0][1], a[0], f0.z, f0.w);
                mma8(acc1[1][1], a[1], f0.z, f0.w);
                mma8(acc1[0][2], a[0], f1.x, f1.y);
                mma8(acc1[1][2], a[1], f1.x, f1.y);
                mma8(acc1[0][3], a[0], f1.z, f1.w);
                mma8(acc1[1][3], a[1], f1.z, f1.w);
            }
        }
        __syncthreads();   // SH src reads + SB reads done
        // ---- h1: bias + SiLU -> SH [128][128] (raw f32, swizzled) ----
#pragma unroll
        for (int nt = 0; nt < 4; nt++) {
            const int k = nw * 32 + nt * 8 + c4 * 2;
            const float2 bv = *(const float2*)(b1 + nc * 128 + k);
            const uint32_t wcol = ((uint32_t)k) ^ sA;
#pragma unroll
            for (int mt = 0; mt < 2; mt++)
#pragma unroll
                for (int h = 0; h < 2; h++) {
                    const int r = ew + mt * 16 + h * 8 + r8;
                    float2 p;
                    p.x = silu_f(acc1[mt][nt][h * 2 + 0] + bv.x);
                    p.y = silu_f(acc1[mt][nt][h * 2 + 1] + bv.y);
                    *(float2*)(SHf + r * 128 + wcol) = p;
                }
        }
        // ---- GEMM2: h2 += h1c @ W2 chunk ----
        float4 w2r = W2f4[(size_t)(nc * 4) * 512 + t];
        for (int s2 = 0; s2 < 4; s2++) {
            float4* SBb4 = (float4*)(SB + (s2 & 1) * 4096);
            SBb4[t] = w2r;
            if (s2 < 3) w2r = W2f4[(size_t)(nc * 4 + s2 + 1) * 512 + t];
            __syncthreads();
            const uint32_t* SBb = SB + (s2 & 1) * 4096;
#pragma unroll
            for (int k8 = 0; k8 < 4; k8++) {
                const uint32_t* SHr = SH + (ew + r8) * 128;
                const uint32_t cb = ((uint32_t)(s2 * 32 + k8 * 8 + c4)) ^ sA;
                uint32_t a[2][4];
                a[0][0] = SHr[cb];            a[0][1] = SHr[1024 + cb];
                a[0][2] = SHr[cb ^ 4u];       a[0][3] = SHr[1024 + (cb ^ 4u)];
                a[1][0] = SHr[2048 + cb];     a[1][1] = SHr[3072 + cb];
                a[1][2] = SHr[2048 + (cb ^ 4u)]; a[1][3] = SHr[3072 + (cb ^ 4u)];
                const uint4 f0 = *((const uint4*)(SBb + k8 * 512 + nw * 128) + lane);
                mma8(acc2[0][0], a[0], f0.x, f0.y);
                mma8(acc2[1][0], a[1], f0.x, f0.y);
                mma8(acc2[0][1], a[0], f0.z, f0.w);
                mma8(acc2[1][1], a[1], f0.z, f0.w);
            }
        }
    }
    __syncthreads();   // GEMM2 SH reads done
    // ---- h2: bias + SiLU -> SH [128][64] ----
#pragma unroll
    for (int nt = 0; nt < 2; nt++) {
        const int k = nw * 16 + nt * 8 + c4 * 2;
        const float2 bv = *(const float2*)(b2 + k);
        const uint32_t wcol = ((uint32_t)k) ^ sA;
#pragma unroll
        for (int mt = 0; mt < 2; mt++)
#pragma unroll
            for (int h = 0; h < 2; h++) {
                const int r = ew + mt * 16 + h * 8 + r8;
                float2 p;
                p.x = silu_f(acc2[mt][nt][h * 2 + 0] + bv.x);
                p.y = silu_f(acc2[mt][nt][h * 2 + 1] + bv.y);
                *(float2*)(SHf + r * 64 + wcol) = p;
            }
    }
    // ---- GEMM3: 4 pipelined stages of 16 k-rows ----
    float acc3[2][4][4];
#pragma unroll
    for (int a = 0; a < 2; a++)
#pragma unroll
        for (int b = 0; b < 4; b++)
#pragma unroll
            for (int c = 0; c < 4; c++) acc3[a][b][c] = 0.f;
    {
        float4 w30 = W3f4[t];
        for (int s3 = 0; s3 < 4; s3++) {
            float4* SBb4 = (float4*)(SB + (s3 & 1) * 4096);
            SBb4[t] = w30;
            if (s3 < 3) w30 = W3f4[(size_t)(s3 + 1) * 512 + t];
            __syncthreads();
            const uint32_t* SBb = SB + (s3 & 1) * 4096;
#pragma unroll
            for (int k8l = 0; k8l < 2; k8l++) {
                const uint32_t* SHr = SH + (ew + r8) * 64;
                const uint32_t cb = ((uint32_t)(s3 * 16 + k8l * 8 + c4)) ^ sA;
                uint32_t a[2][4];
                a[0][0] = SHr[cb];           a[0][1] = SHr[512 + cb];
                a[0][2] = SHr[cb ^ 4u];      a[0][3] = SHr[512 + (cb ^ 4u)];
                a[1][0] = SHr[1024 + cb];    a[1][1] = SHr[1536 + cb];
                a[1][2] = SHr[1024 + (cb ^ 4u)]; a[1][3] = SHr[1536 + (cb ^ 4u)];
                const uint4* Bb = (const uint4*)(SBb + k8l * 1024 + nw * 256) + lane;
                const uint4 f0 = Bb[0];
                const uint4 f1 = Bb[32];
                mma8(acc3[0][0], a[0], f0.x, f0.y);
                mma8(acc3[1][0], a[1], f0.x, f0.y);
                mma8(acc3[0][1], a[0], f0.z, f0.w);
                mma8(acc3[1][1], a[1], f0.z, f0.w);
                mma8(acc3[0][2], a[0], f1.x, f1.y);
                mma8(acc3[1][2], a[1], f1.x, f1.y);
                mma8(acc3[0][3], a[0], f1.z, f1.w);
                mma8(acc3[1][3], a[1], f1.z, f1.w);
            }
        }
    }

    // ---- epilogue: bias, partial sums, store h ----
    float s1 = 0.f, s2s = 0.f;
#pragma unroll
    for (int nt = 0; nt < 4; nt++) {
        const int col = nw * 32 + nt * 8 + c4 * 2;
        const float2 bv = *(const float2*)(b3 + col);
#pragma unroll
        for (int mt = 0; mt < 2; mt++)
#pragma unroll
            for (int h = 0; h < 2; h++) {
                const int r = ew + mt * 16 + h * 8 + r8;
                float2 v;
                v.x = acc3[mt][nt][h * 2 + 0] + bv.x;
                v.y = acc3[mt][nt][h * 2 + 1] + bv.y;
                s1  += v.x + v.y;
                s2s += v.x * v.x + v.y * v.y;
                *(float2*)(g_h + (size_t)(eb + r) * NEMB + col) = v;
            }
    }
    float* RED = (float*)smu;   // alias SA (dead)
    __syncthreads();
    RED[t] = s1; RED[NTHR + t] = s2s;
    __syncthreads();
#pragma unroll
    for (int s = NTHR / 2; s > 0; s >>= 1) {
        if (t < s) { RED[t] += RED[t + s]; RED[NTHR + t] += RED[NTHR + t + s]; }
        __syncthreads();
    }
    if (t == 0) {
        g_part[blockIdx.x * 2]     = RED[0];
        g_part[blockIdx.x * 2 + 1] = RED[NTHR];
    }
}

__global__ void reduce_stats_kernel()
{
    __shared__ double sd[512];
    __shared__ double sq[512];
    const int t = threadIdx.x;
    double a = 0.0, b = 0.0;
    for (int i = t; i < NBLK; i += 512) {
        a += (double)g_part[2 * i];
        b += (double)g_part[2 * i + 1];
    }
    sd[t] = a; sq[t] = b;
    __syncthreads();
    for (int s = 256; s > 0; s >>= 1) {
        if (t < s) { sd[t] += sd[t + s]; sq[t] += sq[t + s]; }
        __syncthreads();
    }
    if (t == 0) {
        const double cnt  = (double)E_TOT * (double)NEMB;
        const double mean = sd[0] / cnt;
        const double var  = sq[0] / cnt - mean * mean;
        g_stats[0] = (float)mean;
        g_stats[1] = (float)(1.0 / sqrt(var + 1e-5));
    }
}

__global__ void __launch_bounds__(256)
pass2_kernel(const float4* __restrict__ g2x, const float4* __restrict__ lnw,
             const float4* __restrict__ lnb, float4* __restrict__ out)
{
    const float mean = g_stats[0];
    const float rstd = g_stats[1];
    const int i = blockIdx.x * blockDim.x + threadIdx.x;
    const float4 h = ((const float4*)g_h)[i];
    const float4 g = g2x[i];
    const float4 w = lnw[i];
    const float4 b = lnb[i];
    float4 o;
    o.x = fmaf((h.x - mean) * rstd, w.x, g.x + b.x);
    o.y = fmaf((h.y - mean) * rstd, w.y, g.y + b.y);
    o.z = fmaf((h.z - mean) * rstd, w.z, g.z + b.z);
    o.w = fmaf((h.w - mean) * rstd, w.w, g.w + b.w);
    out[i] = o;
}

extern "C" void kernel_launch(void* const* d_in, const int* in_sizes, int n_in,
                              void* d_out, int out_size)
{
    const float* gx     = (const float*)d_in[0];
    const float* mx     = (const float*)d_in[1];
    const int*   g2me_i = (const int*)d_in[4];
    const float* g2me_x = (const float*)d_in[5];
    const float* W1 = (const float*)d_in[8];
    const float* b1 = (const float*)d_in[9];
    const float* W2 = (const float*)d_in[10];
    const float* b2 = (const float*)d_in[11];
    const float* W3 = (const float*)d_in[12];
    const float* b3 = (const float*)d_in[13];
    const float* lnw = (const float*)d_in[14];
    const float* lnb = (const float*)d_in[15];
    float* out = (float*)d_out;

    cudaFuncSetAttribute(fused_mlp_kernel,
                         cudaFuncAttributeMaxDynamicSharedMemorySize, SMEM_BYTES);

    prep_w_kernel<<<240, 512>>>(W1, W2, W3);
    fused_mlp_kernel<<<NBLK, NTHR, SMEM_BYTES>>>(gx, mx, g2me_i, g2me_x, b1, b2, b3);
    reduce_stats_kernel<<<1, 512>>>();

    const int n4 = (E_TOT * NEMB) / 4;
    pass2_kernel<<<n4 / 256, 256>>>((const float4*)g2me_x, (const float4*)lnw,
                                    (const float4*)lnb, (float4*)out);
}